// round 6
// baseline (speedup 1.0000x reference)
#include <cuda_runtime.h>
#include <math.h>

constexpr int N_OSC  = 2048;
constexpr int N_SAMP = 16384;
constexpr int LAT    = 32;
constexpr int HALF   = N_OSC * LAT;               // 65536

constexpr int OSC_CHUNK  = 32;
constexpr int SAMP_CHUNK = 1024;
constexpr int THREADS    = 256;
constexpr int SPT        = 4;                      // contiguous samples per thread
constexpr int N_OSC_BLK  = N_OSC / OSC_CHUNK;      // 64
constexpr int N_SAMP_BLK = N_SAMP / SAMP_CHUNK;    // 16

// Partial signals per oscillator block: 64 x 16384 floats = 4 MB
__device__ float    g_scratch[N_OSC_BLK * N_SAMP];
// Per-sample-column arrival counters (zero-init; atomicInc wraps -> self-reset,
// so the pattern is graph-replay safe with no reset pass)
__device__ unsigned g_cnt[N_SAMP_BLK];

// -----------------------------------------------------------------------------
// Single fused kernel. Block = 32 oscillators x 1024 samples, 256 threads.
//   phase 0: 32 threads copy this block's 512B slice of the |latent| passthrough
//   phase 1: fp32 warp-scan prologue -> smem tables (validated R5)
//   phase 2: main loop, 4 FMA + 1 MUFU per (osc,sample), partials -> scratch
//   phase 3: last block per sample-column reduces 64 rows -> mean -> out
// -----------------------------------------------------------------------------
__global__ __launch_bounds__(THREADS, 4)
void osc_kernel(const float* __restrict__ latent, float* __restrict__ out) {
    __shared__ float4 s_pack[OSC_CHUNK * LAT];   // (fp, df, ap, da)  16 KB
    __shared__ float  s_base[OSC_CHUNK * LAT];   // pi*(C_k mod 2)     4 KB
    __shared__ unsigned s_old;

    const int tid     = threadIdx.x;
    const int lane    = tid & 31;
    const int warp    = tid >> 5;
    const int oscBase = blockIdx.y * OSC_CHUNK;
    const float PI_F  = 3.14159265358979323846f;

    // ---- phase 0: param passthrough (1024 blocks x 32 float4 = all 131072) ----
    //   out[16384 : +65536] = |latent[65536:131072]|, out[+65536 : ] = |latent[0:65536]|
    if (tid < 32) {
        const int idx = ((blockIdx.y * N_SAMP_BLK + blockIdx.x) * 32 + tid) * 4;
        const int src = (idx < HALF) ? (HALF + idx) : (idx - HALF);
        const float4 v = *reinterpret_cast<const float4*>(&latent[src]);
        *reinterpret_cast<float4*>(&out[N_SAMP + idx]) =
            make_float4(fabsf(v.x), fabsf(v.y), fabsf(v.z), fabsf(v.w));
    }

    // ---- phase 1: fp32 prologue, 8 warps x 4 oscillators ----
#pragma unroll
    for (int j = 0; j < OSC_CHUNK / 8; ++j) {
        const int o  = warp * (OSC_CHUNK / 8) + j;
        const int go = oscBase + o;
        const float f  = fabsf(latent[(size_t)(N_OSC + go) * LAT + lane]);
        const float a  = fabsf(latent[(size_t)go * LAT + lane]);
        const float fn = __shfl_down_sync(0xffffffffu, f, 1);
        const float an = __shfl_down_sync(0xffffffffu, a, 1);
        const float df = (lane < 31) ? (fn - f) : 0.0f;
        const float da = (lane < 31) ? (an - a) : 0.0f;
        const float t = (lane < 31) ? 256.0f * (f + fn) : 0.0f;
        float sc = t;
#pragma unroll
        for (int d = 1; d < 32; d <<= 1) {
            const float u = __shfl_up_sync(0xffffffffu, sc, d);
            if (lane >= d) sc += u;
        }
        const float f0 = __shfl_sync(0xffffffffu, f, 0);
        const float C  = fmaf(256.0f, f0, sc - t);        // exclusive prefix C_k
        const float r  = fmaf(-2.0f, rintf(0.5f * C), C); // C mod 2, exact
        s_pack[o * LAT + lane] = make_float4(f, df, a, da);
        s_base[o * LAT + lane] = PI_F * r;
    }
    __syncthreads();

    // ---- per-thread sample constants (pre-scaled by pi) ----
    const int i0 = blockIdx.x * SAMP_CHUNK + tid * SPT;
    int k;
    float c1q[SPT], c2q[SPT], w[SPT];
    if (i0 < 256) {
        k = 0;
#pragma unroll
        for (int s = 0; s < SPT; ++s) { c1q[s] = PI_F * (float)(i0 + s - 255); c2q[s] = 0.0f; w[s] = 0.0f; }
    } else if (i0 >= 16128) {
        k = 31;
#pragma unroll
        for (int s = 0; s < SPT; ++s) { c1q[s] = PI_F * (float)(i0 + s - 16127); c2q[s] = 0.0f; w[s] = 0.0f; }
    } else {
        k = (i0 - 256) >> 9;
        const int m0 = (i0 - 256) & 511;
#pragma unroll
        for (int s = 0; s < SPT; ++s) {
            const float mp1 = (float)(m0 + s + 1);
            c1q[s] = PI_F * mp1;
            c2q[s] = PI_F * mp1 * mp1 * (1.0f / 1024.0f);
            w[s]   = ((float)(m0 + s) + 0.5f) * (1.0f / 512.0f);
        }
    }

    // ---- phase 2: main loop ----
    float acc[SPT] = {0.0f, 0.0f, 0.0f, 0.0f};
    const float4* pk = &s_pack[k];
    const float*  bk = &s_base[k];
#pragma unroll 4
    for (int o = 0; o < OSC_CHUNK; ++o) {
        const float4 p  = pk[o * LAT];
        const float  bq = bk[o * LAT];
#pragma unroll
        for (int s = 0; s < SPT; ++s) {
            const float Q   = fmaf(c2q[s], p.y, fmaf(c1q[s], p.x, bq));
            const float sv  = __sinf(Q);
            const float amp = fmaf(w[s], p.w, p.z);
            acc[s] = fmaf(sv, amp, acc[s]);
        }
    }
    *reinterpret_cast<float4*>(&g_scratch[blockIdx.y * N_SAMP + i0]) =
        make_float4(acc[0], acc[1], acc[2], acc[3]);

    // ---- phase 3: last block per sample-column reduces ----
    __threadfence();                       // make partials visible device-wide
    __syncthreads();                       // all stores in this block done
    if (tid == 0)
        s_old = atomicInc(&g_cnt[blockIdx.x], N_OSC_BLK - 1);  // wraps 63 -> 0
    __syncthreads();

    if (s_old == N_OSC_BLK - 1) {          // this is the 64th (last) block
        __threadfence();                   // acquire side
        const int j0 = blockIdx.x * SAMP_CHUNK + tid * 4;
        float4 a0 = make_float4(0.f, 0.f, 0.f, 0.f);
        float4 a1 = a0, a2 = a0, a3 = a0;
#pragma unroll
        for (int b = 0; b < N_OSC_BLK; b += 4) {     // 4 independent chains
            const float4 v0 = *reinterpret_cast<const float4*>(&g_scratch[(b + 0) * N_SAMP + j0]);
            const float4 v1 = *reinterpret_cast<const float4*>(&g_scratch[(b + 1) * N_SAMP + j0]);
            const float4 v2 = *reinterpret_cast<const float4*>(&g_scratch[(b + 2) * N_SAMP + j0]);
            const float4 v3 = *reinterpret_cast<const float4*>(&g_scratch[(b + 3) * N_SAMP + j0]);
            a0.x += v0.x; a0.y += v0.y; a0.z += v0.z; a0.w += v0.w;
            a1.x += v1.x; a1.y += v1.y; a1.z += v1.z; a1.w += v1.w;
            a2.x += v2.x; a2.y += v2.y; a2.z += v2.z; a2.w += v2.w;
            a3.x += v3.x; a3.y += v3.y; a3.z += v3.z; a3.w += v3.w;
        }
        const float sc = 1.0f / (float)N_OSC;
        *reinterpret_cast<float4*>(&out[j0]) = make_float4(
            ((a0.x + a1.x) + (a2.x + a3.x)) * sc,
            ((a0.y + a1.y) + (a2.y + a3.y)) * sc,
            ((a0.z + a1.z) + (a2.z + a3.z)) * sc,
            ((a0.w + a1.w) + (a2.w + a3.w)) * sc);
    }
}

extern "C" void kernel_launch(void* const* d_in, const int* in_sizes, int n_in,
                              void* d_out, int out_size) {
    const float* latent = (const float*)d_in[n_in - 1];
    for (int i = 0; i < n_in; ++i) {
        if (in_sizes[i] == 2 * HALF) { latent = (const float*)d_in[i]; break; }
    }
    float* out = (float*)d_out;

    dim3 grid(N_SAMP_BLK, N_OSC_BLK);                       // 16 x 64 = 1024 blocks
    osc_kernel<<<grid, THREADS>>>(latent, out);
}